// round 16
// baseline (speedup 1.0000x reference)
#include <cuda_runtime.h>
#include <cstdint>

// Embedding gather, single-kernel filter-and-gather. (Final converged form.)
// weight: [1'000'000, 128] f32 (512 MB), index: [2'097'152] i32, out: 1 GB.
//
// NB=32 L2 slices of the table (16 MB each). grid = 32 buckets x 1024 blocks;
// blocks are bucket-contiguous so resident blocks share one slice in L2 and
// repeat rows (~57% of draws) hit in L2 (DRAM reads ~450 MB, not 1045 MB).
//
// Each block re-reads its 2048-entry index slice (the 8 MB index is
// L2-resident), filters for its bucket (~64 matches), compacts (pos, idx)
// pairs into shared memory, then gathers with the half-warp 256-bit ld/st
// pattern (a half-warp moves one 512 B row; 2 row-pairs in flight per warp).
//
// __launch_bounds__(256, 7): caps regs at 32 (measured) so 7 blocks/SM
// reside -- the fastest measured gather configuration of this family.
//
// Series: naive warp/row 381 -> MLP batch 305 -> binned 294 -> fused 267 ->
// NB=16 250 -> filter-fused 242. Traffic ~1.55 GB vs 1.51 GB floor; DRAM
// ~81-82% (write-heavy-mix ceiling). Falsified: bulk-copy pipeline (R7),
// gpu-fence reset (R8, CCTL.IVALL flush), NB=64 (R14).

static constexpr int NB       = 32;
static constexpr int BSHIFT   = 15;               // 2^15 rows per bucket
static constexpr int BPB_LOG2 = 10;               // 1024 blocks per bucket
static constexpr int BPB      = 1 << BPB_LOG2;
static constexpr int IPB      = 2048;             // index slice per block
static constexpr int C        = 16;               // 32 B chunks per 512 B row
static constexpr int LCAP     = 256;              // shared list capacity

__device__ __forceinline__ ulonglong4 ldg256_evict_last(const ulonglong4* p) {
    ulonglong4 v;
    asm volatile("ld.global.nc.L2::evict_last.v4.u64 {%0,%1,%2,%3}, [%4];"
                 : "=l"(v.x), "=l"(v.y), "=l"(v.z), "=l"(v.w)
                 : "l"(p));
    return v;
}

__device__ __forceinline__ void stg256_cs(ulonglong4* p, const ulonglong4& v) {
    asm volatile("st.global.cs.v4.u64 [%0], {%1,%2,%3,%4};"
                 :: "l"(p), "l"(v.x), "l"(v.y), "l"(v.z), "l"(v.w)
                 : "memory");
}

// Statistically unreachable (list cap 256 vs mean 64, sigma ~8); kept correct
// but outside the hot path's register budget.
__device__ __noinline__ void overflow_copy_row(
    const ulonglong4* __restrict__ weight,
    ulonglong4*       __restrict__ out,
    int idx, long long pos)
{
    const ulonglong4* src = &weight[(size_t)idx * C];
    ulonglong4*       dst = &out[pos * C];
#pragma unroll
    for (int c = 0; c < C; c++)
        stg256_cs(&dst[c], ldg256_evict_last(&src[c]));
}

__global__ __launch_bounds__(256, 7) void gather_kernel(
    const ulonglong4* __restrict__ weight,
    const int4*       __restrict__ index4,
    ulonglong4*       __restrict__ out,
    int n_index)
{
    __shared__ int2 list[LCAP];
    __shared__ int  count;

    const int bucket = blockIdx.x >> BPB_LOG2;
    const int lbid   = blockIdx.x & (BPB - 1);
    const int tid    = threadIdx.x;

    if (tid == 0) count = 0;
    __syncthreads();

    // ---- Filter phase: scan this block's 2048-index slice (L2-resident). ----
    const long long tpos = (long long)lbid * IPB + tid * 8;
    if (tpos < n_index) {
        int4 a = __ldg(&index4[tpos / 4]);
        int4 b = __ldg(&index4[tpos / 4 + 1]);
        int idx[8] = {a.x, a.y, a.z, a.w, b.x, b.y, b.z, b.w};
#pragma unroll
        for (int i = 0; i < 8; i++) {
            if ((idx[i] >> BSHIFT) == bucket) {
                int slot = atomicAdd(&count, 1);
                if (slot < LCAP)
                    list[slot] = make_int2((int)(tpos + i), idx[i]);
                else
                    overflow_copy_row(weight, out, idx[i], tpos + i);
            }
        }
    }
    __syncthreads();

    int cnt = count;
    if (cnt > LCAP) cnt = LCAP;

    // ---- Gather phase: half-warp / 256-bit pattern, 2 pairs per pass. ----
    // Warp handles 4 entries as 2 (even,odd) pairs; a half-warp (16 lanes x
    // 32 B) moves one 512 B row. 8 warps x 4 entries = 32 per pass.
    const int lane = tid & 31;
    const int sub  = lane >> 4;                   // 0: even entry, 1: odd entry
    const int l16  = lane & 15;
    const int warp = tid >> 5;

    for (int base = warp * 4; base < cnt; base += 8 * 4) {
        int2 ent[2];
#pragma unroll
        for (int p = 0; p < 2; p++) {
            int e = base + 2 * p + sub;
            ent[p] = (e < cnt) ? list[e] : make_int2(0, 0);
        }

        ulonglong4 v[2];
#pragma unroll
        for (int p = 0; p < 2; p++)
            v[p] = ldg256_evict_last(&weight[(size_t)ent[p].y * C + l16]);

#pragma unroll
        for (int p = 0; p < 2; p++) {
            int e = base + 2 * p + sub;
            if (e < cnt)
                stg256_cs(&out[(size_t)ent[p].x * C + l16], v[p]);
        }
    }
}

extern "C" void kernel_launch(void* const* d_in, const int* in_sizes, int n_in,
                              void* d_out, int out_size)
{
    const ulonglong4* weight = (const ulonglong4*)d_in[0];
    const int4*       index4 = (const int4*)d_in[1];
    ulonglong4*       out    = (ulonglong4*)d_out;

    const int n_index = in_sizes[1];              // 2,097,152 = 1024 * 2048

    gather_kernel<<<NB << BPB_LOG2, 256>>>(weight, index4, out, n_index);
}

// round 17
// speedup vs baseline: 1.3014x; 1.3014x over previous
#include <cuda_runtime.h>
#include <cstdint>

// Embedding gather, single-kernel filter-and-gather. (Exact R12 form — the
// best-measured configuration of this family: 241.8 us.)
// weight: [1'000'000, 128] f32 (512 MB), index: [2'097'152] i32, out: 1 GB.
//
// NB=32 L2 slices of the table (16 MB each). grid = 32 buckets x 1024 blocks;
// blocks are bucket-contiguous so resident blocks share one slice in L2 and
// repeat rows (~57% of draws) hit in L2 (DRAM reads ~450 MB, not 1045 MB).
//
// No scatter/bins: the 8 MB index is L2-resident; each block re-reads its
// 2048-entry index slice, filters for its bucket (~64 matches), compacts
// (pos, idx) pairs into shared memory, then gathers with half-warp 256-bit
// ld/st (a half-warp moves one 512 B row, 2 row-pairs in flight per warp).
//
// NOTE: no minBlocksPerMultiprocessor — forcing 7 blocks/SM on this filter
// variant (R16) capped regs at 32 and caused local-memory spills in the hot
// path (L1 71% busy, DRAM 63%, 318 us). Natural allocation is regs=40,
// occ ~62%, which R12/R13 showed is NOT the limiter: DRAM ~81.5% at the
// write-heavy-mix ceiling, traffic ~1.55 GB vs 1.51 GB floor.
//
// Series: naive warp/row 381 -> MLP batch 305 -> binned 294 -> fused 267 ->
// NB=16 250 -> filter-fused 242. Falsified: bulk-copy pipeline (R7), gpu-
// fence reset (R8, CCTL.IVALL), NB=64 (R14), forced-occupancy hybrid (R16).

static constexpr int NB       = 32;
static constexpr int BSHIFT   = 15;               // 2^15 rows per bucket
static constexpr int BPB_LOG2 = 10;               // 1024 blocks per bucket
static constexpr int BPB      = 1 << BPB_LOG2;
static constexpr int IPB      = 2048;             // index slice per block
static constexpr int C        = 16;               // 32 B chunks per 512 B row
static constexpr int LCAP     = 256;              // shared list capacity

__device__ __forceinline__ ulonglong4 ldg256_evict_last(const ulonglong4* p) {
    ulonglong4 v;
    asm volatile("ld.global.nc.L2::evict_last.v4.u64 {%0,%1,%2,%3}, [%4];"
                 : "=l"(v.x), "=l"(v.y), "=l"(v.z), "=l"(v.w)
                 : "l"(p));
    return v;
}

__device__ __forceinline__ void stg256_cs(ulonglong4* p, const ulonglong4& v) {
    asm volatile("st.global.cs.v4.u64 [%0], {%1,%2,%3,%4};"
                 :: "l"(p), "l"(v.x), "l"(v.y), "l"(v.z), "l"(v.w)
                 : "memory");
}

// Statistically unreachable (list cap 256 vs mean 64); kept correct but out
// of the hot path's register budget.
__device__ __noinline__ void overflow_copy_row(
    const ulonglong4* __restrict__ weight,
    ulonglong4*       __restrict__ out,
    int idx, long long pos)
{
    const ulonglong4* src = &weight[(size_t)idx * C];
    ulonglong4*       dst = &out[pos * C];
#pragma unroll
    for (int c = 0; c < C; c++)
        stg256_cs(&dst[c], ldg256_evict_last(&src[c]));
}

__global__ __launch_bounds__(256) void gather_kernel(
    const ulonglong4* __restrict__ weight,
    const int4*       __restrict__ index4,
    ulonglong4*       __restrict__ out,
    int n_index)
{
    __shared__ int2 list[LCAP];
    __shared__ int  count;

    const int bucket = blockIdx.x >> BPB_LOG2;
    const int lbid   = blockIdx.x & (BPB - 1);
    const int tid    = threadIdx.x;

    if (tid == 0) count = 0;
    __syncthreads();

    // ---- Filter phase: scan this block's 2048-index slice (L2-resident). ----
    const long long tpos = (long long)lbid * IPB + tid * 8;
    if (tpos < n_index) {
        int4 a = __ldg(&index4[tpos / 4]);
        int4 b = __ldg(&index4[tpos / 4 + 1]);
        int idx[8] = {a.x, a.y, a.z, a.w, b.x, b.y, b.z, b.w};
#pragma unroll
        for (int i = 0; i < 8; i++) {
            if ((idx[i] >> BSHIFT) == bucket) {
                int slot = atomicAdd(&count, 1);
                if (slot < LCAP)
                    list[slot] = make_int2((int)(tpos + i), idx[i]);
                else
                    overflow_copy_row(weight, out, idx[i], tpos + i);
            }
        }
    }
    __syncthreads();

    int cnt = count;
    if (cnt > LCAP) cnt = LCAP;

    // ---- Gather phase: half-warp / 256-bit pattern, 2 pairs per pass. ----
    // Warp handles 4 entries as 2 (even,odd) pairs; a half-warp (16 lanes x
    // 32 B) moves one 512 B row. 8 warps x 4 entries = 32 per pass.
    const int lane = tid & 31;
    const int sub  = lane >> 4;                   // 0: even entry, 1: odd entry
    const int l16  = lane & 15;
    const int warp = tid >> 5;

    for (int base = warp * 4; base < cnt; base += 8 * 4) {
        int2 ent[2];
#pragma unroll
        for (int p = 0; p < 2; p++) {
            int e = base + 2 * p + sub;
            ent[p] = (e < cnt) ? list[e] : make_int2(0, 0);
        }

        ulonglong4 v[2];
#pragma unroll
        for (int p = 0; p < 2; p++)
            v[p] = ldg256_evict_last(&weight[(size_t)ent[p].y * C + l16]);

#pragma unroll
        for (int p = 0; p < 2; p++) {
            int e = base + 2 * p + sub;
            if (e < cnt)
                stg256_cs(&out[(size_t)ent[p].x * C + l16], v[p]);
        }
    }
}

extern "C" void kernel_launch(void* const* d_in, const int* in_sizes, int n_in,
                              void* d_out, int out_size)
{
    const ulonglong4* weight = (const ulonglong4*)d_in[0];
    const int4*       index4 = (const int4*)d_in[1];
    ulonglong4*       out    = (ulonglong4*)d_out;

    const int n_index = in_sizes[1];              // 2,097,152 = 1024 * 2048

    gather_kernel<<<NB << BPB_LOG2, 256>>>(weight, index4, out, n_index);
}